// round 10
// baseline (speedup 1.0000x reference)
#include <cuda_runtime.h>

#define EPSC   1e-6f
#define L2E    1.4426950408889634f
#define L2E2C  2.0813689810056077f
#define LN2F   0.6931471805599453f
#define SQRT2  1.41421356237309515f
#define TPB    256
#define NWARP  8
#define ITILE  2
#define JTILE  128
#define MAXPART 2048

__device__ double       g_part[MAXPART];
__device__ unsigned int g_count = 0;

typedef unsigned long long ull;

__device__ __forceinline__ float ex2_approx(float x) {
    float y; asm("ex2.approx.ftz.f32 %0, %1;" : "=f"(y) : "f"(x)); return y;
}
__device__ __forceinline__ float lg2_approx(float x) {
    float y; asm("lg2.approx.ftz.f32 %0, %1;" : "=f"(y) : "f"(x)); return y;
}
__device__ __forceinline__ float sqrt_approx(float x) {
    float y; asm("sqrt.approx.ftz.f32 %0, %1;" : "=f"(y) : "f"(x)); return y;
}
__device__ __forceinline__ ull ffma2(ull a, ull b, ull c) {
    ull d; asm("fma.rn.f32x2 %0, %1, %2, %3;" : "=l"(d) : "l"(a), "l"(b), "l"(c));
    return d;
}
__device__ __forceinline__ ull fmul2(ull a, ull b) {
    ull d; asm("mul.rn.f32x2 %0, %1, %2;" : "=l"(d) : "l"(a), "l"(b));
    return d;
}
__device__ __forceinline__ ull packf2(float lo, float hi) {
    ull r; asm("mov.b64 %0, {%1, %2};" : "=l"(r) : "f"(lo), "f"(hi));
    return r;
}
__device__ __forceinline__ void unpackf2(ull v, float& lo, float& hi) {
    asm("mov.b64 {%0, %1}, %2;" : "=f"(lo), "=f"(hi) : "l"(v));
}

// lgamma(1+x), x in [0,1): A&S 6.1.36 minimax for Gamma(1+x), |eps|<=3e-7.
__device__ __forceinline__ float lgamma1p(float x) {
    float p = 0.035868343f;
    p = fmaf(p, x, -0.193527818f);
    p = fmaf(p, x,  0.482199394f);
    p = fmaf(p, x, -0.756704078f);
    p = fmaf(p, x,  0.918206857f);
    p = fmaf(p, x, -0.897056937f);
    p = fmaf(p, x,  0.988205891f);
    p = fmaf(p, x, -0.577191652f);
    p = fmaf(p, x,  1.0f);
    return lg2_approx(p) * LN2F;
}

union F4U2 { float4 f; ulonglong2 u; };

__global__ void __launch_bounds__(TPB, 5) fused_kernel(
        const float* __restrict__ beta,  const float* __restrict__ gamma,
        const float* __restrict__ zi,    const float* __restrict__ zj,
        const float* __restrict__ vC,
        const int*   __restrict__ si,    const int*   __restrict__ sj,
        const int*   __restrict__ spi,   const int*   __restrict__ spj,
        float* __restrict__ out,
        int S_I, int S_J, int nnz, int gx, int nDense, int nTotal) {

    // j-node 10-vec: (sqrt2*b[0..7], 1, |b|^2) + exp(gamma_j)
    __shared__ ulonglong2 s_jA[JTILE];              // dims 0..3 (sqrt2*b)
    __shared__ ulonglong2 s_jB[JTILE];              // dims 4..7
    __shared__ ulonglong2 s_jC2[JTILE / 2];         // {(1,nj_even),(1,nj_odd)}
    __shared__ __align__(8) float s_je[JTILE];      // exp(gamma_j)
    __shared__ double     ws[NWARP];
    __shared__ bool       s_last;

    const int bid = blockIdx.x;
    const int tid = threadIdx.x;
    const int lane = tid & 31, warp = tid >> 5;

    float dsum = 0.f;    // dense (non-link) partial
    float lsum = 0.f;    // link partial

    if (bid < nDense) {
        // ================= DENSE non-link tile =================
        const int bx = bid % gx, by = bid / gx;

        if (tid < JTILE) {
            int jg = by * JTILE + tid;
            float4 q0 = make_float4(0.f, 0.f, 0.f, 0.f);
            float4 q1 = make_float4(0.f, 0.f, 0.f, 0.f);
            ull   c = 0;      // padded j: whole 10-vec 0 -> contribution 0
            float ej = 0.f;   // ej=0 kills padded j
            if (jg < S_J) {
                int idx = __ldg(sj + jg);
                float4 b0 = __ldg((const float4*)(zj + (size_t)idx * 8));
                float4 b1 = __ldg((const float4*)(zj + (size_t)idx * 8 + 4));
                float nj = b0.x*b0.x + b0.y*b0.y + b0.z*b0.z + b0.w*b0.w
                         + b1.x*b1.x + b1.y*b1.y + b1.z*b1.z + b1.w*b1.w;
                q0 = make_float4(b0.x*SQRT2, b0.y*SQRT2, b0.z*SQRT2, b0.w*SQRT2);
                q1 = make_float4(b1.x*SQRT2, b1.y*SQRT2, b1.z*SQRT2, b1.w*SQRT2);
                c  = packf2(1.0f, nj);
                ej = ex2_approx(__ldg(gamma + idx) * L2E);
            }
            F4U2 c0; c0.f = q0; s_jA[tid] = c0.u;
            F4U2 c1; c1.f = q1; s_jB[tid] = c1.u;
            ((ull*)s_jC2)[tid] = c;
            s_je[tid] = ej;
        }

        // i-node scaled by L2E^2 so dot = L2E^2 * d2 (sqrt -> L2E*d directly):
        // ia = L2E2C * (-sqrt2*(a+eps)[0..7], |a|^2, 1); exp(beta_i) factored out
        ull ia[ITILE][5];
        float ei[ITILE];
        #pragma unroll
        for (int u = 0; u < ITILE; ++u) {
            int ig = bx * (TPB * ITILE) + u * TPB + tid;
            float4 a0 = make_float4(0.f, 0.f, 0.f, 0.f);
            float4 a1 = make_float4(0.f, 0.f, 0.f, 0.f);
            float n = 0.f, e = 0.f;       // pad: e=0 kills the whole row
            if (ig < S_I) {
                int idx = __ldg(si + ig);
                a0 = __ldg((const float4*)(zi + (size_t)idx * 8));
                a1 = __ldg((const float4*)(zi + (size_t)idx * 8 + 4));
                a0.x += EPSC; a0.y += EPSC; a0.z += EPSC; a0.w += EPSC;
                a1.x += EPSC; a1.y += EPSC; a1.z += EPSC; a1.w += EPSC;
                n = a0.x*a0.x + a0.y*a0.y + a0.z*a0.z + a0.w*a0.w
                  + a1.x*a1.x + a1.y*a1.y + a1.z*a1.z + a1.w*a1.w;
                e = ex2_approx(__ldg(beta + idx) * L2E);   // exp(beta_i)
            }
            ei[u] = e;
            const float SC = -SQRT2 * L2E2C;
            ia[u][0] = packf2(SC * a0.x, SC * a0.y);
            ia[u][1] = packf2(SC * a0.z, SC * a0.w);
            ia[u][2] = packf2(SC * a1.x, SC * a1.y);
            ia[u][3] = packf2(SC * a1.z, SC * a1.w);
            ia[u][4] = packf2(n * L2E2C, L2E2C);
        }
        __syncthreads();

        ull sum2[ITILE];
        #pragma unroll
        for (int u = 0; u < ITILE; ++u) sum2[u] = packf2(0.f, 0.f);

        #pragma unroll 2
        for (int j = 0; j < JTILE; j += 2) {
            ulonglong2 A0 = s_jA[j],     B0 = s_jB[j];
            ulonglong2 A1 = s_jA[j + 1], B1 = s_jB[j + 1];
            ulonglong2 C2 = s_jC2[j >> 1];
            ull ej2 = *(const ull*)&s_je[j];         // (ej_j, ej_j+1)
            #pragma unroll
            for (int u = 0; u < ITILE; ++u) {
                ull a = fmul2(ia[u][0], A0.x);
                a = ffma2(ia[u][1], A0.y, a);
                a = ffma2(ia[u][2], B0.x, a);
                a = ffma2(ia[u][3], B0.y, a);
                a = ffma2(ia[u][4], C2.x, a);
                ull b = fmul2(ia[u][0], A1.x);
                b = ffma2(ia[u][1], A1.y, b);
                b = ffma2(ia[u][2], B1.x, b);
                b = ffma2(ia[u][3], B1.y, b);
                b = ffma2(ia[u][4], C2.y, b);
                float la, ha; unpackf2(a, la, ha);
                float lb, hb; unpackf2(b, lb, hb);
                float da = sqrt_approx(la + ha);         // = L2E * dist
                float db = sqrt_approx(lb + hb);
                ull ep = packf2(ex2_approx(-da), ex2_approx(-db));
                sum2[u] = ffma2(ep, ej2, sum2[u]);       // * exp(gamma_j)
            }
        }
        #pragma unroll
        for (int u = 0; u < ITILE; ++u) {
            float lo, hi; unpackf2(sum2[u], lo, hi);
            dsum = fmaf(lo + hi, ei[u], dsum);           // * exp(beta_i)
        }
    }

    // ================= SPARSE link term: all blocks cooperate =================
    {
        int e = bid * TPB + tid;
        int stride = nTotal * TPB;
        #pragma unroll 2
        for (; e < nnz; e += stride) {
            int a = __ldg(spi + e), b = __ldg(spj + e);
            float4 a0 = __ldg((const float4*)(zi + (size_t)a * 8));
            float4 a1 = __ldg((const float4*)(zi + (size_t)a * 8 + 4));
            float4 b0 = __ldg((const float4*)(zj + (size_t)b * 8));
            float4 b1 = __ldg((const float4*)(zj + (size_t)b * 8 + 4));
            float d2 = 0.f, dx;
            dx = a0.x - b0.x + EPSC; d2 = fmaf(dx, dx, d2);
            dx = a0.y - b0.y + EPSC; d2 = fmaf(dx, dx, d2);
            dx = a0.z - b0.z + EPSC; d2 = fmaf(dx, dx, d2);
            dx = a0.w - b0.w + EPSC; d2 = fmaf(dx, dx, d2);
            dx = a1.x - b1.x + EPSC; d2 = fmaf(dx, dx, d2);
            dx = a1.y - b1.y + EPSC; d2 = fmaf(dx, dx, d2);
            dx = a1.z - b1.z + EPSC; d2 = fmaf(dx, dx, d2);
            dx = a1.w - b1.w + EPSC; d2 = fmaf(dx, dx, d2);
            float dist = sqrt_approx(d2);
            float v    = __ldg(vC + e);
            float bias = __ldg(beta + a) + __ldg(gamma + b);
            lsum += fmaf(v, bias - dist, -lgamma1p(v));
        }
    }

    // ---- deterministic block reduction: (link - dense) in double ----
    double t = (double)lsum - (double)dsum;
    #pragma unroll
    for (int o = 16; o; o >>= 1) t += __shfl_down_sync(0xFFFFFFFFu, t, o);
    if (lane == 0) ws[warp] = t;
    __syncthreads();
    if (tid == 0) {
        double b = 0.0;
        #pragma unroll
        for (int k = 0; k < NWARP; ++k) b += ws[k];
        g_part[bid] = b;
        __threadfence();
        unsigned int done = atomicAdd(&g_count, 1u);
        s_last = (done == (unsigned int)(nTotal - 1));
    }
    __syncthreads();

    // ---- last block: final deterministic sum + counter reset ----
    if (s_last) {
        __threadfence();
        double s = 0.0;
        for (int k = tid; k < nTotal; k += TPB) s += __ldcg(&g_part[k]);
        #pragma unroll
        for (int o = 16; o; o >>= 1) s += __shfl_down_sync(0xFFFFFFFFu, s, o);
        __syncthreads();               // ws reuse
        if (lane == 0) ws[warp] = s;
        __syncthreads();
        if (tid == 0) {
            double r = 0.0;
            #pragma unroll
            for (int k = 0; k < NWARP; ++k) r += ws[k];
            out[0] = (float)r;
            g_count = 0;               // reset for next graph replay
        }
    }
}

extern "C" void kernel_launch(void* const* d_in, const int* in_sizes, int n_in,
                              void* d_out, int out_size) {
    const float* beta  = (const float*)d_in[0];
    const float* gamma = (const float*)d_in[1];
    const float* zi    = (const float*)d_in[2];
    const float* zj    = (const float*)d_in[3];
    const float* vC    = (const float*)d_in[4];
    const int*   si    = (const int*)d_in[5];
    const int*   sj    = (const int*)d_in[6];
    const int*   spi   = (const int*)d_in[7];
    const int*   spj   = (const int*)d_in[8];

    int S_I = in_sizes[5];
    int S_J = in_sizes[6];
    int NNZ = in_sizes[4];

    int gx = (S_I + TPB * ITILE - 1) / (TPB * ITILE);   // 12 for 6000
    int gy = (S_J + JTILE - 1) / JTILE;                 // 47 for 6000
    int nDense = gx * gy;                               // 564
    int nTotal = 740;                                   // 5 blocks/SM, one wave
    if (nTotal < nDense + 14) nTotal = nDense + 14;
    if (nTotal > MAXPART) nTotal = MAXPART;

    fused_kernel<<<nTotal, TPB>>>(beta, gamma, zi, zj, vC, si, sj, spi, spj,
                                  (float*)d_out, S_I, S_J, NNZ,
                                  gx, nDense, nTotal);
}

// round 11
// speedup vs baseline: 1.1241x; 1.1241x over previous
#include <cuda_runtime.h>

#define EPSC   1e-6f
#define L2E    1.4426950408889634f
#define L2E2C  2.0813689810056077f
#define LN2F   0.6931471805599453f
#define SQRT2  1.41421356237309515f
#define TPB    256
#define NWARP  8
#define ITILE  2
#define JTILE  128
#define MAXPART 2048

__device__ double       g_part[MAXPART];
__device__ unsigned int g_count = 0;

typedef unsigned long long ull;

__device__ __forceinline__ float ex2_approx(float x) {
    float y; asm("ex2.approx.ftz.f32 %0, %1;" : "=f"(y) : "f"(x)); return y;
}
__device__ __forceinline__ float lg2_approx(float x) {
    float y; asm("lg2.approx.ftz.f32 %0, %1;" : "=f"(y) : "f"(x)); return y;
}
__device__ __forceinline__ float sqrt_approx(float x) {
    float y; asm("sqrt.approx.ftz.f32 %0, %1;" : "=f"(y) : "f"(x)); return y;
}
__device__ __forceinline__ ull ffma2(ull a, ull b, ull c) {
    ull d; asm("fma.rn.f32x2 %0, %1, %2, %3;" : "=l"(d) : "l"(a), "l"(b), "l"(c));
    return d;
}
__device__ __forceinline__ ull fmul2(ull a, ull b) {
    ull d; asm("mul.rn.f32x2 %0, %1, %2;" : "=l"(d) : "l"(a), "l"(b));
    return d;
}
__device__ __forceinline__ ull packf2(float lo, float hi) {
    ull r; asm("mov.b64 %0, {%1, %2};" : "=l"(r) : "f"(lo), "f"(hi));
    return r;
}
__device__ __forceinline__ void unpackf2(ull v, float& lo, float& hi) {
    asm("mov.b64 {%0, %1}, %2;" : "=f"(lo), "=f"(hi) : "l"(v));
}

// lgamma(1+x), x in [0,1): A&S 6.1.36 minimax for Gamma(1+x), |eps|<=3e-7.
__device__ __forceinline__ float lgamma1p(float x) {
    float p = 0.035868343f;
    p = fmaf(p, x, -0.193527818f);
    p = fmaf(p, x,  0.482199394f);
    p = fmaf(p, x, -0.756704078f);
    p = fmaf(p, x,  0.918206857f);
    p = fmaf(p, x, -0.897056937f);
    p = fmaf(p, x,  0.988205891f);
    p = fmaf(p, x, -0.577191652f);
    p = fmaf(p, x,  1.0f);
    return lg2_approx(p) * LN2F;
}

union F4U2 { float4 f; ulonglong2 u; };

__global__ void __launch_bounds__(TPB, 4) fused_kernel(
        const float* __restrict__ beta,  const float* __restrict__ gamma,
        const float* __restrict__ zi,    const float* __restrict__ zj,
        const float* __restrict__ vC,
        const int*   __restrict__ si,    const int*   __restrict__ sj,
        const int*   __restrict__ spi,   const int*   __restrict__ spj,
        float* __restrict__ out,
        int S_I, int S_J, int nnz, int gx, int nDense, int nTotal) {

    // j-node 10-vec: (sqrt2*b[0..7], 1, |b|^2) + exp(gamma_j)
    __shared__ ulonglong2 s_jA[JTILE];              // dims 0..3 (sqrt2*b)
    __shared__ ulonglong2 s_jB[JTILE];              // dims 4..7
    __shared__ ulonglong2 s_jC2[JTILE / 2];         // {(1,nj_even),(1,nj_odd)}
    __shared__ __align__(8) float s_je[JTILE];      // exp(gamma_j)
    __shared__ double     ws[NWARP];
    __shared__ bool       s_last;

    const int bid = blockIdx.x;
    const int tid = threadIdx.x;
    const int lane = tid & 31, warp = tid >> 5;

    float dsum = 0.f;    // dense (non-link) partial
    float lsum = 0.f;    // link partial

    if (bid < nDense) {
        // ================= DENSE non-link tile =================
        const int bx = bid % gx, by = bid / gx;

        if (tid < JTILE) {
            int jg = by * JTILE + tid;
            float4 q0 = make_float4(0.f, 0.f, 0.f, 0.f);
            float4 q1 = make_float4(0.f, 0.f, 0.f, 0.f);
            ull   c = 0;      // padded j: whole 10-vec 0 -> contribution 0
            float ej = 0.f;   // ej=0 kills padded j
            if (jg < S_J) {
                int idx = __ldg(sj + jg);
                float4 b0 = __ldg((const float4*)(zj + (size_t)idx * 8));
                float4 b1 = __ldg((const float4*)(zj + (size_t)idx * 8 + 4));
                float nj = b0.x*b0.x + b0.y*b0.y + b0.z*b0.z + b0.w*b0.w
                         + b1.x*b1.x + b1.y*b1.y + b1.z*b1.z + b1.w*b1.w;
                q0 = make_float4(b0.x*SQRT2, b0.y*SQRT2, b0.z*SQRT2, b0.w*SQRT2);
                q1 = make_float4(b1.x*SQRT2, b1.y*SQRT2, b1.z*SQRT2, b1.w*SQRT2);
                c  = packf2(1.0f, nj);
                ej = ex2_approx(__ldg(gamma + idx) * L2E);
            }
            F4U2 c0; c0.f = q0; s_jA[tid] = c0.u;
            F4U2 c1; c1.f = q1; s_jB[tid] = c1.u;
            ((ull*)s_jC2)[tid] = c;
            s_je[tid] = ej;
        }

        // i-node scaled by L2E^2 so dot = (L2E*d)^2 (sqrt -> L2E*d directly):
        // ia = L2E2C * (-sqrt2*(a+eps)[0..7], |a|^2, 1); exp(beta_i) factored out
        ull ia[ITILE][5];
        float ei[ITILE];
        #pragma unroll
        for (int u = 0; u < ITILE; ++u) {
            int ig = bx * (TPB * ITILE) + u * TPB + tid;
            float4 a0 = make_float4(0.f, 0.f, 0.f, 0.f);
            float4 a1 = make_float4(0.f, 0.f, 0.f, 0.f);
            float n = 0.f, e = 0.f;       // pad: e=0 kills the whole row
            if (ig < S_I) {
                int idx = __ldg(si + ig);
                a0 = __ldg((const float4*)(zi + (size_t)idx * 8));
                a1 = __ldg((const float4*)(zi + (size_t)idx * 8 + 4));
                a0.x += EPSC; a0.y += EPSC; a0.z += EPSC; a0.w += EPSC;
                a1.x += EPSC; a1.y += EPSC; a1.z += EPSC; a1.w += EPSC;
                n = a0.x*a0.x + a0.y*a0.y + a0.z*a0.z + a0.w*a0.w
                  + a1.x*a1.x + a1.y*a1.y + a1.z*a1.z + a1.w*a1.w;
                e = ex2_approx(__ldg(beta + idx) * L2E);   // exp(beta_i)
            }
            ei[u] = e;
            const float SC = -SQRT2 * L2E2C;
            ia[u][0] = packf2(SC * a0.x, SC * a0.y);
            ia[u][1] = packf2(SC * a0.z, SC * a0.w);
            ia[u][2] = packf2(SC * a1.x, SC * a1.y);
            ia[u][3] = packf2(SC * a1.z, SC * a1.w);
            ia[u][4] = packf2(n * L2E2C, L2E2C);
        }
        __syncthreads();

        // 4 independent scalar accumulators: [u][jj]
        float acc00 = 0.f, acc01 = 0.f, acc10 = 0.f, acc11 = 0.f;

        #pragma unroll 2
        for (int j = 0; j < JTILE; j += 2) {
            ulonglong2 A0 = s_jA[j],     B0 = s_jB[j];
            ulonglong2 A1 = s_jA[j + 1], B1 = s_jB[j + 1];
            ulonglong2 C2 = s_jC2[j >> 1];
            float2 ne = *(const float2*)&s_je[j];    // (ej_j, ej_j+1)

            ull a0d = fmul2(ia[0][0], A0.x);
            a0d = ffma2(ia[0][1], A0.y, a0d);
            a0d = ffma2(ia[0][2], B0.x, a0d);
            a0d = ffma2(ia[0][3], B0.y, a0d);
            a0d = ffma2(ia[0][4], C2.x, a0d);
            ull a1d = fmul2(ia[0][0], A1.x);
            a1d = ffma2(ia[0][1], A1.y, a1d);
            a1d = ffma2(ia[0][2], B1.x, a1d);
            a1d = ffma2(ia[0][3], B1.y, a1d);
            a1d = ffma2(ia[0][4], C2.y, a1d);
            ull b0d = fmul2(ia[1][0], A0.x);
            b0d = ffma2(ia[1][1], A0.y, b0d);
            b0d = ffma2(ia[1][2], B0.x, b0d);
            b0d = ffma2(ia[1][3], B0.y, b0d);
            b0d = ffma2(ia[1][4], C2.x, b0d);
            ull b1d = fmul2(ia[1][0], A1.x);
            b1d = ffma2(ia[1][1], A1.y, b1d);
            b1d = ffma2(ia[1][2], B1.x, b1d);
            b1d = ffma2(ia[1][3], B1.y, b1d);
            b1d = ffma2(ia[1][4], C2.y, b1d);

            // scalar epilogue: FADD -> SQRT -> EX2(-.) -> FFMA, 4 indep chains
            float l0, h0; unpackf2(a0d, l0, h0);
            float l1, h1; unpackf2(a1d, l1, h1);
            float l2, h2; unpackf2(b0d, l2, h2);
            float l3, h3; unpackf2(b1d, l3, h3);
            float d0 = sqrt_approx(l0 + h0);   // = L2E*dist
            float d1 = sqrt_approx(l1 + h1);
            float d2 = sqrt_approx(l2 + h2);
            float d3 = sqrt_approx(l3 + h3);
            acc00 = fmaf(ex2_approx(-d0), ne.x, acc00);
            acc01 = fmaf(ex2_approx(-d1), ne.y, acc01);
            acc10 = fmaf(ex2_approx(-d2), ne.x, acc10);
            acc11 = fmaf(ex2_approx(-d3), ne.y, acc11);
        }
        dsum = fmaf(acc00 + acc01, ei[0], dsum);     // * exp(beta_i)
        dsum = fmaf(acc10 + acc11, ei[1], dsum);
    }

    // ================= SPARSE link term: all blocks cooperate =================
    {
        int e = bid * TPB + tid;
        int stride = nTotal * TPB;
        #pragma unroll 2
        for (; e < nnz; e += stride) {
            int a = __ldg(spi + e), b = __ldg(spj + e);
            float4 a0 = __ldg((const float4*)(zi + (size_t)a * 8));
            float4 a1 = __ldg((const float4*)(zi + (size_t)a * 8 + 4));
            float4 b0 = __ldg((const float4*)(zj + (size_t)b * 8));
            float4 b1 = __ldg((const float4*)(zj + (size_t)b * 8 + 4));
            float d2 = 0.f, dx;
            dx = a0.x - b0.x + EPSC; d2 = fmaf(dx, dx, d2);
            dx = a0.y - b0.y + EPSC; d2 = fmaf(dx, dx, d2);
            dx = a0.z - b0.z + EPSC; d2 = fmaf(dx, dx, d2);
            dx = a0.w - b0.w + EPSC; d2 = fmaf(dx, dx, d2);
            dx = a1.x - b1.x + EPSC; d2 = fmaf(dx, dx, d2);
            dx = a1.y - b1.y + EPSC; d2 = fmaf(dx, dx, d2);
            dx = a1.z - b1.z + EPSC; d2 = fmaf(dx, dx, d2);
            dx = a1.w - b1.w + EPSC; d2 = fmaf(dx, dx, d2);
            float dist = sqrt_approx(d2);
            float v    = __ldg(vC + e);
            float bias = __ldg(beta + a) + __ldg(gamma + b);
            lsum += fmaf(v, bias - dist, -lgamma1p(v));
        }
    }

    // ---- deterministic block reduction: (link - dense) in double ----
    double t = (double)lsum - (double)dsum;
    #pragma unroll
    for (int o = 16; o; o >>= 1) t += __shfl_down_sync(0xFFFFFFFFu, t, o);
    if (lane == 0) ws[warp] = t;
    __syncthreads();
    if (tid == 0) {
        double b = 0.0;
        #pragma unroll
        for (int k = 0; k < NWARP; ++k) b += ws[k];
        g_part[bid] = b;
        __threadfence();
        unsigned int done = atomicAdd(&g_count, 1u);
        s_last = (done == (unsigned int)(nTotal - 1));
    }
    __syncthreads();

    // ---- last block: final deterministic sum + counter reset ----
    if (s_last) {
        __threadfence();
        double s = 0.0;
        for (int k = tid; k < nTotal; k += TPB) s += __ldcg(&g_part[k]);
        #pragma unroll
        for (int o = 16; o; o >>= 1) s += __shfl_down_sync(0xFFFFFFFFu, s, o);
        __syncthreads();               // ws reuse
        if (lane == 0) ws[warp] = s;
        __syncthreads();
        if (tid == 0) {
            double r = 0.0;
            #pragma unroll
            for (int k = 0; k < NWARP; ++k) r += ws[k];
            out[0] = (float)r;
            g_count = 0;               // reset for next graph replay
        }
    }
}

extern "C" void kernel_launch(void* const* d_in, const int* in_sizes, int n_in,
                              void* d_out, int out_size) {
    const float* beta  = (const float*)d_in[0];
    const float* gamma = (const float*)d_in[1];
    const float* zi    = (const float*)d_in[2];
    const float* zj    = (const float*)d_in[3];
    const float* vC    = (const float*)d_in[4];
    const int*   si    = (const int*)d_in[5];
    const int*   sj    = (const int*)d_in[6];
    const int*   spi   = (const int*)d_in[7];
    const int*   spj   = (const int*)d_in[8];

    int S_I = in_sizes[5];
    int S_J = in_sizes[6];
    int NNZ = in_sizes[4];

    int gx = (S_I + TPB * ITILE - 1) / (TPB * ITILE);   // 12 for 6000
    int gy = (S_J + JTILE - 1) / JTILE;                 // 47 for 6000
    int nDense = gx * gy;                               // 564
    int nTotal = nDense + 28;                           // 592 = 4 blocks/SM wave
    if (nTotal > MAXPART) nTotal = MAXPART;

    fused_kernel<<<nTotal, TPB>>>(beta, gamma, zi, zj, vC, si, sj, spi, spj,
                                  (float*)d_out, S_I, S_J, NNZ,
                                  gx, nDense, nTotal);
}